// round 16
// baseline (speedup 1.0000x reference)
#include <cuda_runtime.h>
#include <cuda_fp16.h>
#include <cstdint>

#define T_STEPS 64
#define BATCH   32
#define IDIM    128
#define HDIM    256
#define MROWS   (T_STEPS * BATCH)   // 2048
#define KTOT    65536               // (j,c) contraction
#define JGROUPS 9                   // 4 groups of 29 j + 5 groups of 28 j
#define CTX_CL  4

// ---------------- scratch (__device__ globals; no allocations allowed) ----------------
__device__ __half g_iph[MROWS * HDIM];
__device__ float  g_xc [MROWS * HDIM];
__device__ __half g_ctxh[MROWS * HDIM];
__device__ float  g_wtv_c2c[HDIM * HDIM];
__device__ float  g_wtv_i2h[HDIM * IDIM];
__device__ float  g_wtv_i2c[HDIM * IDIM];
__device__ float  g_btv    [HDIM * HDIM];
__device__ __half g_bhi[(size_t)HDIM * KTOT];   // pre-swizzled 64-k chunk images (hi only)
__device__ float  g_part[(size_t)JGROUPS * MROWS * HDIM];

// ---------------- small PTX helpers (base ISA only — no "a" features) ----------------
__device__ __forceinline__ uint32_t smem_u32(const void* p) {
    uint32_t a;
    asm("{ .reg .u64 t; cvta.to.shared.u64 t, %1; cvt.u32.u64 %0, t; }" : "=r"(a) : "l"(p));
    return a;
}
__device__ __forceinline__ void cp16(uint32_t dst, const void* src) {
    asm volatile("cp.async.cg.shared.global [%0], [%1], 16;" :: "r"(dst), "l"(src));
}
#define CP_COMMIT() asm volatile("cp.async.commit_group;" ::: "memory")
#define CP_WAIT0()  asm volatile("cp.async.wait_group 0;" ::: "memory")

__device__ __forceinline__ void ldsm_x4(uint32_t* r, uint32_t addr) {
    asm volatile("ldmatrix.sync.aligned.m8n8.x4.shared.b16 {%0,%1,%2,%3}, [%4];"
                 : "=r"(r[0]), "=r"(r[1]), "=r"(r[2]), "=r"(r[3]) : "r"(addr));
}
__device__ __forceinline__ void ldsm_x4t(uint32_t* r, uint32_t addr) {
    asm volatile("ldmatrix.sync.aligned.m8n8.x4.trans.shared.b16 {%0,%1,%2,%3}, [%4];"
                 : "=r"(r[0]), "=r"(r[1]), "=r"(r[2]), "=r"(r[3]) : "r"(addr));
}
__device__ __forceinline__ void mma16816(float* d, const uint32_t* a,
                                         uint32_t b0, uint32_t b1) {
    asm volatile(
        "mma.sync.aligned.m16n8k16.row.col.f32.f16.f16.f32 "
        "{%0,%1,%2,%3},{%4,%5,%6,%7},{%8,%9},{%0,%1,%2,%3};"
        : "+f"(d[0]), "+f"(d[1]), "+f"(d[2]), "+f"(d[3])
        : "r"(a[0]), "r"(a[1]), "r"(a[2]), "r"(a[3]), "r"(b0), "r"(b1));
}
__device__ __forceinline__ uint32_t pkh(__half a, __half b) {
    __half2 p = __halves2half2(a, b);
    return *(uint32_t*)&p;
}
__device__ __forceinline__ uint32_t hmul2u(uint32_t a, __half2 b) {
    __half2 r = __hmul2(*(__half2*)&a, b);
    return *(uint32_t*)&r;
}
__device__ __forceinline__ uint32_t mapa_cl(uint32_t addr, uint32_t rank) {
    uint32_t r;
    asm("mapa.shared::cluster.u32 %0, %1, %2;" : "=r"(r) : "r"(addr), "r"(rank));
    return r;
}

// ---------------- all 4 transposes in one launch ----------------
__global__ void tvec_all_kernel(const float* __restrict__ w_c2c,
                                const float* __restrict__ w_i2h,
                                const float* __restrict__ w_i2c,
                                const float* __restrict__ b_c2t) {
    int blk = blockIdx.x;
    const float* in;
    float* out;
    int K;
    if (blk < 256)        { in = w_c2c; out = g_wtv_c2c; K = HDIM; }
    else if (blk < 384)   { in = w_i2h; out = g_wtv_i2h; K = IDIM; blk -= 256; }
    else if (blk < 512)   { in = w_i2c; out = g_wtv_i2c; K = IDIM; blk -= 384; }
    else                  { in = b_c2t; out = g_btv;     K = HDIM; blk -= 512; }
    int idx = blk * 256 + threadIdx.x;
    int i = idx / K;
    int k = idx - i * K;
    out[(k >> 2) * (HDIM * 4) + i * 4 + (k & 3)] = in[idx];
}

// ---------------- fp16 (hi-only) image of w_c2t as pre-swizzled 64-c chunk images ---
//   phys(c,i) = c*512 + (((i>>3) ^ (c&7)) << 4) + (i&7)*2
__global__ void bsplit_kernel(const float* __restrict__ w) {
    extern __shared__ float s[];                // [256][65]
    int kc = blockIdx.x;                        // 0..1023
    int j = kc >> 2, cb = kc & 3;
    int base = j * 256 + cb * 64;
    int tid = threadIdx.x;
    for (int u = tid; u < 256 * 16; u += 256) {
        int i = u >> 4, f = u & 15;
        float4 v = *(const float4*)(w + (size_t)i * KTOT + base + f * 4);
        s[i * 65 + f * 4 + 0] = v.x;
        s[i * 65 + f * 4 + 1] = v.y;
        s[i * 65 + f * 4 + 2] = v.z;
        s[i * 65 + f * 4 + 3] = v.w;
    }
    __syncthreads();
    char* oh = (char*)(g_bhi + (size_t)kc * 16384);
#pragma unroll
    for (int it = 0; it < 8; it++) {
        int u = tid + it * 256;
        int c = u >> 5, ib = u & 31;
        uint32_t ph[4];
#pragma unroll
        for (int e = 0; e < 4; e++) {
            float w0 = s[(ib * 8 + 2 * e + 0) * 65 + c];
            float w1 = s[(ib * 8 + 2 * e + 1) * 65 + c];
            ph[e] = pkh(__float2half_rn(w0), __float2half_rn(w1));
        }
        uint32_t off = c * 512 + ((ib ^ (c & 7)) << 4);
        *(uint4*)(oh + off) = make_uint4(ph[0], ph[1], ph[2], ph[3]);
    }
}

// ---------------- m-tiled projections + bconst (8 rows/CTA, weights read once) ------
#define PROJ_MT 8
__global__ void __launch_bounds__(256, 1)
projb_kernel(const float* __restrict__ x,
             const float* __restrict__ b_i2h,
             const float* __restrict__ b_i2c,
             float* __restrict__ out) {
    __shared__ __align__(16) float xs[PROJ_MT][IDIM];
    __shared__ __align__(16) float ips[PROJ_MT][HDIM];
    int m0 = blockIdx.x * PROJ_MT;
    int i = threadIdx.x;
    {
        int u = i;
        int m = u >> 5, k4 = u & 31;
        ((float4*)&xs[m][0])[k4] = *(const float4*)(x + (size_t)(m0 + m) * IDIM + k4 * 4);
    }
    __syncthreads();

    float a1[PROJ_MT], a2[PROJ_MT];
    float bh = b_i2h[i], bc = b_i2c[i];
#pragma unroll
    for (int m = 0; m < PROJ_MT; m++) { a1[m] = bh; a2[m] = bc; }

#pragma unroll 4
    for (int k4 = 0; k4 < IDIM / 4; k4++) {
        float4 w1 = *(const float4*)&g_wtv_i2h[k4 * (HDIM * 4) + i * 4];
        float4 w2 = *(const float4*)&g_wtv_i2c[k4 * (HDIM * 4) + i * 4];
#pragma unroll
        for (int m = 0; m < PROJ_MT; m++) {
            float4 xv = ((const float4*)&xs[m][0])[k4];
            a1[m] += w1.x * xv.x + w1.y * xv.y + w1.z * xv.z + w1.w * xv.w;
            a2[m] += w2.x * xv.x + w2.y * xv.y + w2.z * xv.z + w2.w * xv.w;
        }
    }
#pragma unroll
    for (int m = 0; m < PROJ_MT; m++) {
        g_iph[(size_t)(m0 + m) * HDIM + i] = __float2half_rn(a1[m]);
        g_xc [(size_t)(m0 + m) * HDIM + i] = a2[m];
        ips[m][i] = a1[m];
    }
    __syncthreads();

    float ba[PROJ_MT];
#pragma unroll
    for (int m = 0; m < PROJ_MT; m++) ba[m] = 0.f;
#pragma unroll 4
    for (int j4 = 0; j4 < HDIM / 4; j4++) {
        float4 w = *(const float4*)&g_btv[j4 * (HDIM * 4) + i * 4];
#pragma unroll
        for (int m = 0; m < PROJ_MT; m++) {
            float4 pv = ((const float4*)&ips[m][0])[j4];
            ba[m] += w.x * pv.x + w.y * pv.y + w.z * pv.z + w.w * pv.w;
        }
    }
#pragma unroll
    for (int m = 0; m < PROJ_MT; m++)
        out[(size_t)(m0 + m) * HDIM + i] = ba[m];
}

// ---------------- context trajectory: 4-CTA cluster per sample (R12/R14 config) -----
// Micro-opt: g_xc for step t+1 is prefetched BEFORE the cluster barrier so its L2
// latency drains under the barrier instead of being exposed at the top of each step.
#define CTX_SMEM ((16384 + 256 + 2048) * 4)

__global__ void __launch_bounds__(256, 1) __cluster_dims__(CTX_CL, 1, 1)
ctx_kernel(const float* __restrict__ b_c2c,
           float* __restrict__ out_ctx_final) {
    extern __shared__ float smc[];
    float4* ws4 = (float4*)smc;                  // [16][256] float4
    float*  cs  = smc + 16384;
    float*  mb  = smc + 16640;                   // [2][4][256]
    uint32_t smb = smem_u32(smc);
    uint32_t mb_u = smb + 16640 * 4;

    uint32_t crank;
    asm("mov.u32 %0, %%cluster_ctarank;" : "=r"(crank));
    int b = blockIdx.x >> 2;
    int i = threadIdx.x;

    {
        const float4* src = (const float4*)g_wtv_c2c + crank * 4096;
        for (int u = i; u < 4096; u += 256) ws4[u] = src[u];
    }
    float rb = b_c2c[i];
    float myctx = 0.f;
    cs[i] = 0.f;
    float xcv_next = g_xc[(0 * BATCH + b) * HDIM + i];   // prefetch t=0
    __syncthreads();

    const float4* cs4 = (const float4*)cs;
    const int cbase4 = (int)crank * 16;

    for (int t = 0; t < T_STEPS; t++) {
        if (crank == 0) g_ctxh[(t * BATCH + b) * HDIM + i] = __float2half_rn(myctx);
        float xcv = xcv_next;

        float s0 = 0.f, s1 = 0.f, s2 = 0.f, s3 = 0.f;
#pragma unroll
        for (int c4 = 0; c4 < 16; c4++) {
            float4 w = ws4[c4 * 256 + i];
            float4 cv = cs4[cbase4 + c4];
            s0 += w.x * cv.x;
            s1 += w.y * cv.y;
            s2 += w.z * cv.z;
            s3 += w.w * cv.w;
        }
        float part = (s0 + s1) + (s2 + s3);

        int p = t & 1;
        uint32_t off = (uint32_t)(((p * 4 + crank) * 256 + i) * 4);
        mb[(p * 4 + crank) * 256 + i] = part;
#pragma unroll
        for (uint32_t r = 0; r < 4; r++) {
            if (r != crank) {
                uint32_t ra = mapa_cl(mb_u + off, r);
                asm volatile("st.shared::cluster.f32 [%0], %1;"
                             :: "r"(ra), "f"(part) : "memory");
            }
        }
        // prefetch next step's xc: latency hides under the cluster barrier
        if (t + 1 < T_STEPS)
            xcv_next = g_xc[((t + 1) * BATCH + b) * HDIM + i];

        asm volatile("barrier.cluster.arrive.aligned;" ::: "memory");
        asm volatile("barrier.cluster.wait.aligned;" ::: "memory");

        float tot = (mb[(p * 4 + 0) * 256 + i] + mb[(p * 4 + 1) * 256 + i])
                  + (mb[(p * 4 + 2) * 256 + i] + mb[(p * 4 + 3) * 256 + i]);
        float cn = fmaxf(rb + xcv + tot, 0.f);
        myctx = 0.8f * myctx + 0.2f * cn;
        cs[i] = myctx;
        __syncthreads();
    }
    if (crank == 0) out_ctx_final[b * HDIM + i] = myctx;
}

// ---------------- mma.sync hypernet GEMM (R14 config: pipelined produce) ------------
#define A_OFF   0
#define B_OFF   16384
#define STAGE   49152
#define GEMM_SMEM (2 * STAGE)      // 98304 B

// A phys: m*128 + ((c/8 ^ m%8)<<4) + (c%8)*2
// B phys: c*512 + ((i/8 ^ c%8)<<4) + (i%8)*2

__global__ void __launch_bounds__(512, 1)
hyper_kernel() {
    extern __shared__ char sm[];
    uint32_t smb = smem_u32(sm);
    int tid = threadIdx.x;
    int lane = tid & 31, wid = tid >> 5;
    int warp_m = wid >> 2, warp_i = wid & 3;     // 4 x 4
    int mb = warp_m * 32, ib = warp_i * 64;
    const int m0 = blockIdx.x * 128;
    const int jg = blockIdx.y;
    const int jstart = (jg < 4) ? jg * 29 : 116 + (jg - 4) * 28;
    const int nchunks = ((jg < 4) ? 29 : 28) * 4;

    float acc[2][8][4];
#pragma unroll
    for (int a = 0; a < 2; a++)
#pragma unroll
        for (int b = 0; b < 8; b++)
#pragma unroll
            for (int c = 0; c < 4; c++) acc[a][b][c] = 0.f;

    int lr  = lane & 7;
    int l8  = lane & 8;
    int l16 = (lane & 16) ? 8 : 0;

    const int pm = tid >> 2, pq = tid & 3;
    const int prow = m0 + pm;
    const int psw = pm & 7;
    __half hip;
    uint4 cva, cvb;

    {   // prologue: produce chunk 0 into stage 0
        int j = jstart;
        const char* srch = (const char*)(g_bhi + (size_t)(j * 4 + 0) * 16384);
        uint32_t dst = smb + 0 * STAGE;
#pragma unroll
        for (int it = 0; it < 4; it++) {
            int u = tid + it * 512;
            cp16(dst + B_OFF + u * 16, srch + (size_t)u * 16);
        }
        CP_COMMIT();
        hip = g_iph[prow * HDIM + j];
        const uint4* cp_ = (const uint4*)&g_ctxh[prow * HDIM + 0 * 64 + pq * 16];
        cva = cp_[0];
        cvb = cp_[1];
        __half2 ip2 = __half2half2(hip);
        char* arow = sm + 0 * STAGE + A_OFF + pm * 128;
        *(uint4*)(arow + (((pq * 2 + 0) ^ psw) << 4)) =
            make_uint4(hmul2u(cva.x, ip2), hmul2u(cva.y, ip2),
                       hmul2u(cva.z, ip2), hmul2u(cva.w, ip2));
        *(uint4*)(arow + (((pq * 2 + 1) ^ psw) << 4)) =
            make_uint4(hmul2u(cvb.x, ip2), hmul2u(cvb.y, ip2),
                       hmul2u(cvb.z, ip2), hmul2u(cvb.w, ip2));
    }
    CP_WAIT0();
    __syncthreads();

    for (int nc = 0; nc < nchunks; nc++) {
        int s = nc & 1;
        bool more = (nc + 1 < nchunks);

        if (more) {   // load-phase for chunk nc+1
            int nn = nc + 1;
            int jl = nn >> 2, cbk = nn & 3;
            int j = jstart + jl;
            const char* srch = (const char*)(g_bhi + (size_t)(j * 4 + cbk) * 16384);
            uint32_t dst = smb + (s ^ 1) * STAGE;
#pragma unroll
            for (int it = 0; it < 4; it++) {
                int u = tid + it * 512;
                cp16(dst + B_OFF + u * 16, srch + (size_t)u * 16);
            }
            CP_COMMIT();
            hip = g_iph[prow * HDIM + j];
            const uint4* cp_ = (const uint4*)&g_ctxh[prow * HDIM + cbk * 64 + pq * 16];
            cva = cp_[0];
            cvb = cp_[1];
        }

        uint32_t Ab = smb + s * STAGE + A_OFF;
        uint32_t Bb = smb + s * STAGE + B_OFF;

#pragma unroll
        for (int kt = 0; kt < 64; kt += 16) {
            uint32_t a[2][4];
#pragma unroll
            for (int mi = 0; mi < 2; mi++) {
                int mrow = mb + mi * 16 + lr + l8;
                uint32_t ad = Ab + mrow * 128 + (((((kt + l16) >> 3)) ^ (mrow & 7)) << 4);
                ldsm_x4(a[mi], ad);
            }
            uint32_t b[16];
#pragma unroll
            for (int t = 0; t < 4; t++) {
                int c = kt + lr + l8;
                int iu = (ib + t * 16 + l16) >> 3;
                ldsm_x4t(&b[t * 4], Bb + c * 512 + ((iu ^ (c & 7)) << 4));
            }
#pragma unroll
            for (int mi = 0; mi < 2; mi++)
#pragma unroll
                for (int ni = 0; ni < 8; ni++)
                    mma16816(acc[mi][ni], a[mi], b[(ni >> 1) * 4 + (ni & 1) * 2],
                             b[(ni >> 1) * 4 + (ni & 1) * 2 + 1]);
        }

        if (more) {   // store-phase for chunk nc+1
            __half2 ip2 = __half2half2(hip);
            char* arow = sm + (s ^ 1) * STAGE + A_OFF + pm * 128;
            *(uint4*)(arow + (((pq * 2 + 0) ^ psw) << 4)) =
                make_uint4(hmul2u(cva.x, ip2), hmul2u(cva.y, ip2),
                           hmul2u(cva.z, ip2), hmul2u(cva.w, ip2));
            *(uint4*)(arow + (((pq * 2 + 1) ^ psw) << 4)) =
                make_uint4(hmul2u(cvb.x, ip2), hmul2u(cvb.y, ip2),
                           hmul2u(cvb.z, ip2), hmul2u(cvb.w, ip2));
        }
        CP_WAIT0();
        __syncthreads();
    }

    int g = lane >> 2, tg = lane & 3;
    float* base = g_part + ((size_t)jg * MROWS) * HDIM;
#pragma unroll
    for (int mi = 0; mi < 2; mi++) {
#pragma unroll
        for (int ni = 0; ni < 8; ni++) {
            int row = m0 + mb + mi * 16 + g;
            int col = ib + ni * 8 + tg * 2;
            *(float2*)&base[(size_t)row * HDIM + col] =
                make_float2(acc[mi][ni][0], acc[mi][ni][1]);
            *(float2*)&base[(size_t)(row + 8) * HDIM + col] =
                make_float2(acc[mi][ni][2], acc[mi][ni][3]);
        }
    }
}

// ---------------- reduction (+ fused hidden copy): out += sum(partials) -------------
__global__ void reduce_kernel(float* __restrict__ out) {
    int i = blockIdx.x * blockDim.x + threadIdx.x;   // float4 units, 0..131071
    float4* o4 = (float4*)out;
    float4 v = o4[i];
    const float4* p4 = (const float4*)g_part;
#pragma unroll
    for (int s = 0; s < JGROUPS; s++) {
        float4 p = p4[(size_t)s * (MROWS * HDIM / 4) + i];
        v.x += p.x; v.y += p.y; v.z += p.z; v.w += p.w;
    }
    o4[i] = v;
    // hidden = transformed at t = T-1
    if (i >= (MROWS - BATCH) * HDIM / 4)
        o4[i + BATCH * HDIM / 4] = v;
}

// ---------------- launch (R14-proven topology: ONE side stream, TWO events) ---------
extern "C" void kernel_launch(void* const* d_in, const int* in_sizes, int n_in,
                              void* d_out, int out_size) {
    const float* x      = (const float*)d_in[0];
    const float* w_i2h  = (const float*)d_in[1];
    const float* b_i2h  = (const float*)d_in[2];
    // d_in[3]/d_in[4] = w_h2h/b_h2h: dead in the reference (hidden overwritten)
    const float* w_i2c  = (const float*)d_in[5];
    const float* b_i2c  = (const float*)d_in[6];
    const float* w_c2c  = (const float*)d_in[7];
    const float* b_c2c  = (const float*)d_in[8];
    const float* w_c2t  = (const float*)d_in[9];
    const float* b_c2t  = (const float*)d_in[10];
    float* out = (float*)d_out;
    (void)in_sizes; (void)n_in; (void)out_size;

    // side stream for bsplit (independent of the tvec->projb->ctx chain).
    cudaStream_t s1;
    cudaEvent_t e1, e2;
    cudaStreamCreateWithFlags(&s1, cudaStreamNonBlocking);
    cudaEventCreateWithFlags(&e1, cudaEventDisableTiming);
    cudaEventCreateWithFlags(&e2, cudaEventDisableTiming);

    cudaEventRecord(e1, 0);
    cudaStreamWaitEvent(s1, e1, 0);
    cudaFuncSetAttribute(bsplit_kernel,
                         cudaFuncAttributeMaxDynamicSharedMemorySize, 256 * 65 * 4);
    bsplit_kernel<<<1024, 256, 256 * 65 * 4, s1>>>(w_c2t);
    cudaEventRecord(e2, s1);

    tvec_all_kernel<<<768, 256>>>(w_c2c, w_i2h, w_i2c, b_c2t);
    projb_kernel<<<MROWS / PROJ_MT, 256>>>(x, b_i2h, b_i2c, out);

    cudaFuncSetAttribute(ctx_kernel,
                         cudaFuncAttributeMaxDynamicSharedMemorySize, CTX_SMEM);
    ctx_kernel<<<BATCH * CTX_CL, 256, CTX_SMEM>>>(b_c2c, out + MROWS * HDIM + BATCH * HDIM);

    cudaStreamWaitEvent(0, e2, 0);   // join bsplit before the GEMM
    cudaFuncSetAttribute(hyper_kernel,
                         cudaFuncAttributeMaxDynamicSharedMemorySize, GEMM_SMEM);
    hyper_kernel<<<dim3(MROWS / 128, JGROUPS), 512, GEMM_SMEM>>>();

    reduce_kernel<<<(MROWS * HDIM / 4) / 256, 256>>>(out);
}

// round 17
// speedup vs baseline: 1.0662x; 1.0662x over previous
#include <cuda_runtime.h>
#include <cuda_fp16.h>
#include <cstdint>

#define T_STEPS 64
#define BATCH   32
#define IDIM    128
#define HDIM    256
#define MROWS   (T_STEPS * BATCH)   // 2048
#define KTOT    65536               // (j,c) contraction
#define JGROUPS 9                   // 4 groups of 29 j + 5 groups of 28 j
#define CTX_CL  4

// ---------------- scratch (__device__ globals; no allocations allowed) ----------------
__device__ __half g_iph[MROWS * HDIM];
__device__ float  g_xc [MROWS * HDIM];
__device__ __half g_ctxh[MROWS * HDIM];
__device__ float  g_wtv_c2c[HDIM * HDIM];
__device__ float  g_wtv_i2h[HDIM * IDIM];
__device__ float  g_wtv_i2c[HDIM * IDIM];
__device__ float  g_btv    [HDIM * HDIM];
__device__ __half g_bhi[(size_t)HDIM * KTOT];   // pre-swizzled 64-k chunk images (hi only)
__device__ float  g_part[(size_t)JGROUPS * MROWS * HDIM];

// ---------------- small PTX helpers (base ISA only — no "a" features) ----------------
__device__ __forceinline__ uint32_t smem_u32(const void* p) {
    uint32_t a;
    asm("{ .reg .u64 t; cvta.to.shared.u64 t, %1; cvt.u32.u64 %0, t; }" : "=r"(a) : "l"(p));
    return a;
}
__device__ __forceinline__ void cp16(uint32_t dst, const void* src) {
    asm volatile("cp.async.cg.shared.global [%0], [%1], 16;" :: "r"(dst), "l"(src));
}
#define CP_COMMIT() asm volatile("cp.async.commit_group;" ::: "memory")
#define CP_WAIT0()  asm volatile("cp.async.wait_group 0;" ::: "memory")

__device__ __forceinline__ void ldsm_x4(uint32_t* r, uint32_t addr) {
    asm volatile("ldmatrix.sync.aligned.m8n8.x4.shared.b16 {%0,%1,%2,%3}, [%4];"
                 : "=r"(r[0]), "=r"(r[1]), "=r"(r[2]), "=r"(r[3]) : "r"(addr));
}
__device__ __forceinline__ void ldsm_x4t(uint32_t* r, uint32_t addr) {
    asm volatile("ldmatrix.sync.aligned.m8n8.x4.trans.shared.b16 {%0,%1,%2,%3}, [%4];"
                 : "=r"(r[0]), "=r"(r[1]), "=r"(r[2]), "=r"(r[3]) : "r"(addr));
}
__device__ __forceinline__ void mma16816(float* d, const uint32_t* a,
                                         uint32_t b0, uint32_t b1) {
    asm volatile(
        "mma.sync.aligned.m16n8k16.row.col.f32.f16.f16.f32 "
        "{%0,%1,%2,%3},{%4,%5,%6,%7},{%8,%9},{%0,%1,%2,%3};"
        : "+f"(d[0]), "+f"(d[1]), "+f"(d[2]), "+f"(d[3])
        : "r"(a[0]), "r"(a[1]), "r"(a[2]), "r"(a[3]), "r"(b0), "r"(b1));
}
__device__ __forceinline__ uint32_t pkh(__half a, __half b) {
    __half2 p = __halves2half2(a, b);
    return *(uint32_t*)&p;
}
__device__ __forceinline__ uint32_t hmul2u(uint32_t a, __half2 b) {
    __half2 r = __hmul2(*(__half2*)&a, b);
    return *(uint32_t*)&r;
}
__device__ __forceinline__ uint32_t mapa_cl(uint32_t addr, uint32_t rank) {
    uint32_t r;
    asm("mapa.shared::cluster.u32 %0, %1, %2;" : "=r"(r) : "r"(addr), "r"(rank));
    return r;
}

// ---------------- all 4 transposes in one launch ----------------
__global__ void tvec_all_kernel(const float* __restrict__ w_c2c,
                                const float* __restrict__ w_i2h,
                                const float* __restrict__ w_i2c,
                                const float* __restrict__ b_c2t) {
    int blk = blockIdx.x;
    const float* in;
    float* out;
    int K;
    if (blk < 256)        { in = w_c2c; out = g_wtv_c2c; K = HDIM; }
    else if (blk < 384)   { in = w_i2h; out = g_wtv_i2h; K = IDIM; blk -= 256; }
    else if (blk < 512)   { in = w_i2c; out = g_wtv_i2c; K = IDIM; blk -= 384; }
    else                  { in = b_c2t; out = g_btv;     K = HDIM; blk -= 512; }
    int idx = blk * 256 + threadIdx.x;
    int i = idx / K;
    int k = idx - i * K;
    out[(k >> 2) * (HDIM * 4) + i * 4 + (k & 3)] = in[idx];
}

// ---------------- fp16 (hi-only) image of w_c2t as pre-swizzled 64-c chunk images ---
//   phys(c,i) = c*512 + (((i>>3) ^ (c&7)) << 4) + (i&7)*2
__global__ void bsplit_kernel(const float* __restrict__ w) {
    extern __shared__ float s[];                // [256][65]
    int kc = blockIdx.x;                        // 0..1023
    int j = kc >> 2, cb = kc & 3;
    int base = j * 256 + cb * 64;
    int tid = threadIdx.x;
    for (int u = tid; u < 256 * 16; u += 256) {
        int i = u >> 4, f = u & 15;
        float4 v = *(const float4*)(w + (size_t)i * KTOT + base + f * 4);
        s[i * 65 + f * 4 + 0] = v.x;
        s[i * 65 + f * 4 + 1] = v.y;
        s[i * 65 + f * 4 + 2] = v.z;
        s[i * 65 + f * 4 + 3] = v.w;
    }
    __syncthreads();
    char* oh = (char*)(g_bhi + (size_t)kc * 16384);
#pragma unroll
    for (int it = 0; it < 8; it++) {
        int u = tid + it * 256;
        int c = u >> 5, ib = u & 31;
        uint32_t ph[4];
#pragma unroll
        for (int e = 0; e < 4; e++) {
            float w0 = s[(ib * 8 + 2 * e + 0) * 65 + c];
            float w1 = s[(ib * 8 + 2 * e + 1) * 65 + c];
            ph[e] = pkh(__float2half_rn(w0), __float2half_rn(w1));
        }
        uint32_t off = c * 512 + ((ib ^ (c & 7)) << 4);
        *(uint4*)(oh + off) = make_uint4(ph[0], ph[1], ph[2], ph[3]);
    }
}

// ---------------- m-tiled projections + bconst (8 rows/CTA, weights read once) ------
#define PROJ_MT 8
__global__ void __launch_bounds__(256, 1)
projb_kernel(const float* __restrict__ x,
             const float* __restrict__ b_i2h,
             const float* __restrict__ b_i2c,
             float* __restrict__ out) {
    __shared__ __align__(16) float xs[PROJ_MT][IDIM];
    __shared__ __align__(16) float ips[PROJ_MT][HDIM];
    int m0 = blockIdx.x * PROJ_MT;
    int i = threadIdx.x;
    {
        int u = i;
        int m = u >> 5, k4 = u & 31;
        ((float4*)&xs[m][0])[k4] = *(const float4*)(x + (size_t)(m0 + m) * IDIM + k4 * 4);
    }
    __syncthreads();

    float a1[PROJ_MT], a2[PROJ_MT];
    float bh = b_i2h[i], bc = b_i2c[i];
#pragma unroll
    for (int m = 0; m < PROJ_MT; m++) { a1[m] = bh; a2[m] = bc; }

#pragma unroll 4
    for (int k4 = 0; k4 < IDIM / 4; k4++) {
        float4 w1 = *(const float4*)&g_wtv_i2h[k4 * (HDIM * 4) + i * 4];
        float4 w2 = *(const float4*)&g_wtv_i2c[k4 * (HDIM * 4) + i * 4];
#pragma unroll
        for (int m = 0; m < PROJ_MT; m++) {
            float4 xv = ((const float4*)&xs[m][0])[k4];
            a1[m] += w1.x * xv.x + w1.y * xv.y + w1.z * xv.z + w1.w * xv.w;
            a2[m] += w2.x * xv.x + w2.y * xv.y + w2.z * xv.z + w2.w * xv.w;
        }
    }
#pragma unroll
    for (int m = 0; m < PROJ_MT; m++) {
        g_iph[(size_t)(m0 + m) * HDIM + i] = __float2half_rn(a1[m]);
        g_xc [(size_t)(m0 + m) * HDIM + i] = a2[m];
        ips[m][i] = a1[m];
    }
    __syncthreads();

    float ba[PROJ_MT];
#pragma unroll
    for (int m = 0; m < PROJ_MT; m++) ba[m] = 0.f;
#pragma unroll 4
    for (int j4 = 0; j4 < HDIM / 4; j4++) {
        float4 w = *(const float4*)&g_btv[j4 * (HDIM * 4) + i * 4];
#pragma unroll
        for (int m = 0; m < PROJ_MT; m++) {
            float4 pv = ((const float4*)&ips[m][0])[j4];
            ba[m] += w.x * pv.x + w.y * pv.y + w.z * pv.z + w.w * pv.w;
        }
    }
#pragma unroll
    for (int m = 0; m < PROJ_MT; m++)
        out[(size_t)(m0 + m) * HDIM + i] = ba[m];
}

// ---------------- context trajectory: 4-CTA cluster, register-resident weights ------
// Thread i holds its 64 w[i][c] values (c in crank's slice) in 16 float4 registers;
// the per-step dot reads only the broadcast cs[] from smem. Sync structure = R14.
#define CTX_SMEM ((256 + 2048) * 4)

__global__ void __launch_bounds__(256, 1) __cluster_dims__(CTX_CL, 1, 1)
ctx_kernel(const float* __restrict__ b_c2c,
           float* __restrict__ out_ctx_final) {
    extern __shared__ float smc[];
    float* cs = smc;                             // [256]
    float* mb = smc + 256;                       // [2][4][256]
    uint32_t smb = smem_u32(smc);
    uint32_t mb_u = smb + 256 * 4;

    uint32_t crank;
    asm("mov.u32 %0, %%cluster_ctarank;" : "=r"(crank));
    int b = blockIdx.x >> 2;
    int i = threadIdx.x;

    // loop-invariant weights -> registers (coalesced one-time load)
    float4 wreg[16];
    {
        const float4* src = (const float4*)g_wtv_c2c + (size_t)crank * 4096;
#pragma unroll
        for (int c4 = 0; c4 < 16; c4++) wreg[c4] = src[c4 * 256 + i];
    }
    float rb = b_c2c[i];
    float myctx = 0.f;
    cs[i] = 0.f;
    __syncthreads();

    const float4* cs4 = (const float4*)cs;
    const int cbase4 = (int)crank * 16;

    for (int t = 0; t < T_STEPS; t++) {
        if (crank == 0) g_ctxh[(t * BATCH + b) * HDIM + i] = __float2half_rn(myctx);
        float xcv = g_xc[(t * BATCH + b) * HDIM + i];

        float s0 = 0.f, s1 = 0.f, s2 = 0.f, s3 = 0.f;
#pragma unroll
        for (int c4 = 0; c4 < 16; c4++) {
            float4 cv = cs4[cbase4 + c4];
            s0 += wreg[c4].x * cv.x;
            s1 += wreg[c4].y * cv.y;
            s2 += wreg[c4].z * cv.z;
            s3 += wreg[c4].w * cv.w;
        }
        float part = (s0 + s1) + (s2 + s3);

        int p = t & 1;
        uint32_t off = (uint32_t)(((p * 4 + crank) * 256 + i) * 4);
        mb[(p * 4 + crank) * 256 + i] = part;
#pragma unroll
        for (uint32_t r = 0; r < 4; r++) {
            if (r != crank) {
                uint32_t ra = mapa_cl(mb_u + off, r);
                asm volatile("st.shared::cluster.f32 [%0], %1;"
                             :: "r"(ra), "f"(part) : "memory");
            }
        }
        asm volatile("barrier.cluster.arrive.aligned;" ::: "memory");
        asm volatile("barrier.cluster.wait.aligned;" ::: "memory");

        float tot = (mb[(p * 4 + 0) * 256 + i] + mb[(p * 4 + 1) * 256 + i])
                  + (mb[(p * 4 + 2) * 256 + i] + mb[(p * 4 + 3) * 256 + i]);
        float cn = fmaxf(rb + xcv + tot, 0.f);
        myctx = 0.8f * myctx + 0.2f * cn;
        cs[i] = myctx;
        __syncthreads();
    }
    if (crank == 0) out_ctx_final[b * HDIM + i] = myctx;
}

// ---------------- mma.sync hypernet GEMM (R14 config: pipelined produce) ------------
#define A_OFF   0
#define B_OFF   16384
#define STAGE   49152
#define GEMM_SMEM (2 * STAGE)      // 98304 B

// A phys: m*128 + ((c/8 ^ m%8)<<4) + (c%8)*2
// B phys: c*512 + ((i/8 ^ c%8)<<4) + (i%8)*2

__global__ void __launch_bounds__(512, 1)
hyper_kernel() {
    extern __shared__ char sm[];
    uint32_t smb = smem_u32(sm);
    int tid = threadIdx.x;
    int lane = tid & 31, wid = tid >> 5;
    int warp_m = wid >> 2, warp_i = wid & 3;     // 4 x 4
    int mb = warp_m * 32, ib = warp_i * 64;
    const int m0 = blockIdx.x * 128;
    const int jg = blockIdx.y;
    const int jstart = (jg < 4) ? jg * 29 : 116 + (jg - 4) * 28;
    const int nchunks = ((jg < 4) ? 29 : 28) * 4;

    float acc[2][8][4];
#pragma unroll
    for (int a = 0; a < 2; a++)
#pragma unroll
        for (int b = 0; b < 8; b++)
#pragma unroll
            for (int c = 0; c < 4; c++) acc[a][b][c] = 0.f;

    int lr  = lane & 7;
    int l8  = lane & 8;
    int l16 = (lane & 16) ? 8 : 0;

    const int pm = tid >> 2, pq = tid & 3;
    const int prow = m0 + pm;
    const int psw = pm & 7;
    __half hip;
    uint4 cva, cvb;

    {   // prologue: produce chunk 0 into stage 0
        int j = jstart;
        const char* srch = (const char*)(g_bhi + (size_t)(j * 4 + 0) * 16384);
        uint32_t dst = smb + 0 * STAGE;
#pragma unroll
        for (int it = 0; it < 4; it++) {
            int u = tid + it * 512;
            cp16(dst + B_OFF + u * 16, srch + (size_t)u * 16);
        }
        CP_COMMIT();
        hip = g_iph[prow * HDIM + j];
        const uint4* cp_ = (const uint4*)&g_ctxh[prow * HDIM + 0 * 64 + pq * 16];
        cva = cp_[0];
        cvb = cp_[1];
        __half2 ip2 = __half2half2(hip);
        char* arow = sm + 0 * STAGE + A_OFF + pm * 128;
        *(uint4*)(arow + (((pq * 2 + 0) ^ psw) << 4)) =
            make_uint4(hmul2u(cva.x, ip2), hmul2u(cva.y, ip2),
                       hmul2u(cva.z, ip2), hmul2u(cva.w, ip2));
        *(uint4*)(arow + (((pq * 2 + 1) ^ psw) << 4)) =
            make_uint4(hmul2u(cvb.x, ip2), hmul2u(cvb.y, ip2),
                       hmul2u(cvb.z, ip2), hmul2u(cvb.w, ip2));
    }
    CP_WAIT0();
    __syncthreads();

    for (int nc = 0; nc < nchunks; nc++) {
        int s = nc & 1;
        bool more = (nc + 1 < nchunks);

        if (more) {   // load-phase for chunk nc+1
            int nn = nc + 1;
            int jl = nn >> 2, cbk = nn & 3;
            int j = jstart + jl;
            const char* srch = (const char*)(g_bhi + (size_t)(j * 4 + cbk) * 16384);
            uint32_t dst = smb + (s ^ 1) * STAGE;
#pragma unroll
            for (int it = 0; it < 4; it++) {
                int u = tid + it * 512;
                cp16(dst + B_OFF + u * 16, srch + (size_t)u * 16);
            }
            CP_COMMIT();
            hip = g_iph[prow * HDIM + j];
            const uint4* cp_ = (const uint4*)&g_ctxh[prow * HDIM + cbk * 64 + pq * 16];
            cva = cp_[0];
            cvb = cp_[1];
        }

        uint32_t Ab = smb + s * STAGE + A_OFF;
        uint32_t Bb = smb + s * STAGE + B_OFF;

#pragma unroll
        for (int kt = 0; kt < 64; kt += 16) {
            uint32_t a[2][4];
#pragma unroll
            for (int mi = 0; mi < 2; mi++) {
                int mrow = mb + mi * 16 + lr + l8;
                uint32_t ad = Ab + mrow * 128 + (((((kt + l16) >> 3)) ^ (mrow & 7)) << 4);
                ldsm_x4(a[mi], ad);
            }
            uint32_t b[16];
#pragma unroll
            for (int t = 0; t < 4; t++) {
                int c = kt + lr + l8;
                int iu = (ib + t * 16 + l16) >> 3;
                ldsm_x4t(&b[t * 4], Bb + c * 512 + ((iu ^ (c & 7)) << 4));
            }
#pragma unroll
            for (int mi = 0; mi < 2; mi++)
#pragma unroll
                for (int ni = 0; ni < 8; ni++)
                    mma16816(acc[mi][ni], a[mi], b[(ni >> 1) * 4 + (ni & 1) * 2],
                             b[(ni >> 1) * 4 + (ni & 1) * 2 + 1]);
        }

        if (more) {   // store-phase for chunk nc+1
            __half2 ip2 = __half2half2(hip);
            char* arow = sm + (s ^ 1) * STAGE + A_OFF + pm * 128;
            *(uint4*)(arow + (((pq * 2 + 0) ^ psw) << 4)) =
                make_uint4(hmul2u(cva.x, ip2), hmul2u(cva.y, ip2),
                           hmul2u(cva.z, ip2), hmul2u(cva.w, ip2));
            *(uint4*)(arow + (((pq * 2 + 1) ^ psw) << 4)) =
                make_uint4(hmul2u(cvb.x, ip2), hmul2u(cvb.y, ip2),
                           hmul2u(cvb.z, ip2), hmul2u(cvb.w, ip2));
        }
        CP_WAIT0();
        __syncthreads();
    }

    int g = lane >> 2, tg = lane & 3;
    float* base = g_part + ((size_t)jg * MROWS) * HDIM;
#pragma unroll
    for (int mi = 0; mi < 2; mi++) {
#pragma unroll
        for (int ni = 0; ni < 8; ni++) {
            int row = m0 + mb + mi * 16 + g;
            int col = ib + ni * 8 + tg * 2;
            *(float2*)&base[(size_t)row * HDIM + col] =
                make_float2(acc[mi][ni][0], acc[mi][ni][1]);
            *(float2*)&base[(size_t)(row + 8) * HDIM + col] =
                make_float2(acc[mi][ni][2], acc[mi][ni][3]);
        }
    }
}

// ---------------- reduction (+ fused hidden copy): out += sum(partials) -------------
__global__ void reduce_kernel(float* __restrict__ out) {
    int i = blockIdx.x * blockDim.x + threadIdx.x;   // float4 units, 0..131071
    float4* o4 = (float4*)out;
    float4 v = o4[i];
    const float4* p4 = (const float4*)g_part;
#pragma unroll
    for (int s = 0; s < JGROUPS; s++) {
        float4 p = p4[(size_t)s * (MROWS * HDIM / 4) + i];
        v.x += p.x; v.y += p.y; v.z += p.z; v.w += p.w;
    }
    o4[i] = v;
    // hidden = transformed at t = T-1
    if (i >= (MROWS - BATCH) * HDIM / 4)
        o4[i + BATCH * HDIM / 4] = v;
}

// ---------------- launch (R14-proven topology: ONE side stream, TWO events) ---------
extern "C" void kernel_launch(void* const* d_in, const int* in_sizes, int n_in,
                              void* d_out, int out_size) {
    const float* x      = (const float*)d_in[0];
    const float* w_i2h  = (const float*)d_in[1];
    const float* b_i2h  = (const float*)d_in[2];
    // d_in[3]/d_in[4] = w_h2h/b_h2h: dead in the reference (hidden overwritten)
    const float* w_i2c  = (const float*)d_in[5];
    const float* b_i2c  = (const float*)d_in[6];
    const float* w_c2c  = (const float*)d_in[7];
    const float* b_c2c  = (const float*)d_in[8];
    const float* w_c2t  = (const float*)d_in[9];
    const float* b_c2t  = (const float*)d_in[10];
    float* out = (float*)d_out;
    (void)in_sizes; (void)n_in; (void)out_size;

    // side stream for bsplit (independent of the tvec->projb->ctx chain).
    cudaStream_t s1;
    cudaEvent_t e1, e2;
    cudaStreamCreateWithFlags(&s1, cudaStreamNonBlocking);
    cudaEventCreateWithFlags(&e1, cudaEventDisableTiming);
    cudaEventCreateWithFlags(&e2, cudaEventDisableTiming);

    cudaEventRecord(e1, 0);
    cudaStreamWaitEvent(s1, e1, 0);
    cudaFuncSetAttribute(bsplit_kernel,
                         cudaFuncAttributeMaxDynamicSharedMemorySize, 256 * 65 * 4);
    bsplit_kernel<<<1024, 256, 256 * 65 * 4, s1>>>(w_c2t);
    cudaEventRecord(e2, s1);

    tvec_all_kernel<<<768, 256>>>(w_c2c, w_i2h, w_i2c, b_c2t);
    projb_kernel<<<MROWS / PROJ_MT, 256>>>(x, b_i2h, b_i2c, out);

    cudaFuncSetAttribute(ctx_kernel,
                         cudaFuncAttributeMaxDynamicSharedMemorySize, CTX_SMEM);
    ctx_kernel<<<BATCH * CTX_CL, 256, CTX_SMEM>>>(b_c2c, out + MROWS * HDIM + BATCH * HDIM);

    cudaStreamWaitEvent(0, e2, 0);   // join bsplit before the GEMM
    cudaFuncSetAttribute(hyper_kernel,
                         cudaFuncAttributeMaxDynamicSharedMemorySize, GEMM_SMEM);
    hyper_kernel<<<dim3(MROWS / 128, JGROUPS), 512, GEMM_SMEM>>>();

    reduce_kernel<<<(MROWS * HDIM / 4) / 256, 256>>>(out);
}